// round 2
// baseline (speedup 1.0000x reference)
#include <cuda_runtime.h>

#define D_IN   768
#define D_SAE  12288
#define T_LEN  64
#define KTOP   64
#define BATCH  32
#define NROWS  (BATCH * T_LEN)   // 2048

// ---------------- scratch (static device globals; no allocations) ----------------
__device__ __align__(16) float g_pre[(size_t)NROWS * D_SAE];     // 96 MB
__device__ int   g_topidx[NROWS * 128];
__device__ float g_topval[NROWS * 128];
__device__ int   g_zidx[NROWS * KTOP];
__device__ float g_zval[NROWS * KTOP];
__device__ float g_rowloss[NROWS];

// ---------------- helpers ----------------
__device__ __forceinline__ unsigned long long pack2(float x, float y) {
    unsigned long long r;
    asm("mov.b64 %0, {%1, %2};" : "=l"(r) : "f"(x), "f"(y));
    return r;
}
__device__ __forceinline__ float2 unpack2(unsigned long long v) {
    float2 f;
    asm("mov.b64 {%0, %1}, %2;" : "=f"(f.x), "=f"(f.y) : "l"(v));
    return f;
}
__device__ __forceinline__ void fma2(unsigned long long& c, unsigned long long a, unsigned long long b) {
    asm("fma.rn.f32x2 %0, %1, %2, %0;" : "+l"(c) : "l"(a), "l"(b));
}

// total-order key for floats (monotonic uint)
__device__ __forceinline__ unsigned int fkey(float v) {
    unsigned int u = __float_as_uint(v);
    return (u & 0x80000000u) ? ~u : (u | 0x80000000u);
}
__device__ __forceinline__ float keyToFloat(unsigned int k) {
    unsigned int u = (k & 0x80000000u) ? (k & 0x7FFFFFFFu) : ~k;
    return __uint_as_float(u);
}
// composite: larger == (greater value) or (equal value, smaller index)  [jax top_k tie rule]
__device__ __forceinline__ unsigned long long makeComp(float v, int idx) {
    return ((unsigned long long)fkey(v) << 32) | (unsigned long long)(0xFFFFFFFFu - (unsigned int)idx);
}

// ======================================================================
// Kernel A: fp32 GEMM  pre[2048,12288] = X[2048,768] @ W[768,12288] + b
// 128x128 tile, BK=16, 256 threads, 8x8 per thread, f32x2 packed FMA.
// ======================================================================
__global__ __launch_bounds__(256, 1) void gemm_enc(const float* __restrict__ X,
                                                   const float* __restrict__ W,
                                                   const float* __restrict__ bias) {
    __shared__ __align__(16) float As[2][16][128];
    __shared__ __align__(16) float Bs[2][16][128];

    const int tid  = threadIdx.x;
    const int row0 = blockIdx.y * 128;
    const int col0 = blockIdx.x * 128;
    const int tx = tid & 15, ty = tid >> 4;

    const int aRow = tid >> 2;           // 0..63
    const int aCol = (tid & 3) * 4;      // 0,4,8,12
    const int bRow = tid >> 5;           // 0..7
    const int bCol = (tid & 31) * 4;     // 0..124

    const float* Aptr = X + (size_t)row0 * D_IN;
    const float* Bptr = W + col0;

    float4 a0, a1, b0, b1;
    // stage tile 0
    a0 = *(const float4*)(Aptr + (size_t)aRow * D_IN + aCol);
    a1 = *(const float4*)(Aptr + (size_t)(aRow + 64) * D_IN + aCol);
    b0 = *(const float4*)(Bptr + (size_t)bRow * D_SAE + bCol);
    b1 = *(const float4*)(Bptr + (size_t)(bRow + 8) * D_SAE + bCol);
    As[0][aCol + 0][aRow] = a0.x; As[0][aCol + 1][aRow] = a0.y;
    As[0][aCol + 2][aRow] = a0.z; As[0][aCol + 3][aRow] = a0.w;
    As[0][aCol + 0][aRow + 64] = a1.x; As[0][aCol + 1][aRow + 64] = a1.y;
    As[0][aCol + 2][aRow + 64] = a1.z; As[0][aCol + 3][aRow + 64] = a1.w;
    *(float4*)&Bs[0][bRow][bCol]     = b0;
    *(float4*)&Bs[0][bRow + 8][bCol] = b1;
    __syncthreads();

    unsigned long long cc[4][8];
#pragma unroll
    for (int i = 0; i < 4; ++i)
#pragma unroll
        for (int j = 0; j < 8; ++j) cc[i][j] = 0ull;   // two packed 0.0f

    const int NKT = D_IN / 16;  // 48
    for (int kt = 0; kt < NKT; ++kt) {
        const int cur = kt & 1;
        if (kt < NKT - 1) {
            const int k0 = (kt + 1) * 16;
            a0 = *(const float4*)(Aptr + (size_t)aRow * D_IN + k0 + aCol);
            a1 = *(const float4*)(Aptr + (size_t)(aRow + 64) * D_IN + k0 + aCol);
            b0 = *(const float4*)(Bptr + (size_t)(k0 + bRow) * D_SAE + bCol);
            b1 = *(const float4*)(Bptr + (size_t)(k0 + bRow + 8) * D_SAE + bCol);
        }
#pragma unroll
        for (int k = 0; k < 16; ++k) {
            ulonglong2 aa01 = *(const ulonglong2*)&As[cur][k][ty * 4];
            ulonglong2 aa23 = *(const ulonglong2*)&As[cur][k][64 + ty * 4];
            float4 bv0 = *(const float4*)&Bs[cur][k][tx * 4];
            float4 bv1 = *(const float4*)&Bs[cur][k][64 + tx * 4];
            unsigned long long av[4] = {aa01.x, aa01.y, aa23.x, aa23.y};
            unsigned long long bb[8] = {pack2(bv0.x, bv0.x), pack2(bv0.y, bv0.y),
                                        pack2(bv0.z, bv0.z), pack2(bv0.w, bv0.w),
                                        pack2(bv1.x, bv1.x), pack2(bv1.y, bv1.y),
                                        pack2(bv1.z, bv1.z), pack2(bv1.w, bv1.w)};
#pragma unroll
            for (int i = 0; i < 4; ++i)
#pragma unroll
                for (int j = 0; j < 8; ++j) fma2(cc[i][j], av[i], bb[j]);
        }
        if (kt < NKT - 1) {
            const int nxt = cur ^ 1;
            As[nxt][aCol + 0][aRow] = a0.x; As[nxt][aCol + 1][aRow] = a0.y;
            As[nxt][aCol + 2][aRow] = a0.z; As[nxt][aCol + 3][aRow] = a0.w;
            As[nxt][aCol + 0][aRow + 64] = a1.x; As[nxt][aCol + 1][aRow + 64] = a1.y;
            As[nxt][aCol + 2][aRow + 64] = a1.z; As[nxt][aCol + 3][aRow + 64] = a1.w;
            *(float4*)&Bs[nxt][bRow][bCol]     = b0;
            *(float4*)&Bs[nxt][bRow + 8][bCol] = b1;
        }
        __syncthreads();
    }

    // epilogue: add bias, store (float4 along N)
    float bc[8];
#pragma unroll
    for (int j = 0; j < 8; ++j) bc[j] = bias[col0 + (j >> 2) * 64 + tx * 4 + (j & 3)];

#pragma unroll
    for (int i = 0; i < 4; ++i) {
        const int m = (i >> 1) * 64 + ty * 4 + (i & 1) * 2;   // rows m, m+1
        float2 v[8];
#pragma unroll
        for (int j = 0; j < 8; ++j) v[j] = unpack2(cc[i][j]);
        size_t base = (size_t)(row0 + m) * D_SAE + col0;
        float4 o;
        o.x = v[0].x + bc[0]; o.y = v[1].x + bc[1]; o.z = v[2].x + bc[2]; o.w = v[3].x + bc[3];
        *(float4*)&g_pre[base + tx * 4] = o;
        o.x = v[4].x + bc[4]; o.y = v[5].x + bc[5]; o.z = v[6].x + bc[6]; o.w = v[7].x + bc[7];
        *(float4*)&g_pre[base + 64 + tx * 4] = o;
        base += D_SAE;
        o.x = v[0].y + bc[0]; o.y = v[1].y + bc[1]; o.z = v[2].y + bc[2]; o.w = v[3].y + bc[3];
        *(float4*)&g_pre[base + tx * 4] = o;
        o.x = v[4].y + bc[4]; o.y = v[5].y + bc[5]; o.z = v[6].y + bc[6]; o.w = v[7].y + bc[7];
        *(float4*)&g_pre[base + 64 + tx * 4] = o;
    }
}

// ======================================================================
// Kernel B: exact top-128 per row via 12-bit histogram radix select.
// Order of the output list is irrelevant (it's only a candidate superset).
// ======================================================================
#define TK_CAP 3072
__global__ __launch_bounds__(256) void topk128() {
    __shared__ unsigned int hist[4096];
    __shared__ unsigned long long cand[TK_CAP];
    __shared__ unsigned int chunkSum[16];
    __shared__ int s_bin;
    __shared__ unsigned int s_above, s_cntHi, s_cntCand;

    const int row = blockIdx.x, tid = threadIdx.x;
    const float* rp = g_pre + (size_t)row * D_SAE;

    for (int i = tid; i < 4096; i += 256) hist[i] = 0;
    if (tid == 0) { s_cntHi = 0; s_cntCand = 0; }
    __syncthreads();

    for (int i = tid; i < D_SAE / 4; i += 256) {
        float4 v = *(const float4*)(rp + i * 4);
        atomicAdd(&hist[fkey(v.x) >> 20], 1u);
        atomicAdd(&hist[fkey(v.y) >> 20], 1u);
        atomicAdd(&hist[fkey(v.z) >> 20], 1u);
        atomicAdd(&hist[fkey(v.w) >> 20], 1u);
    }
    __syncthreads();

    if (tid < 16) {
        unsigned int s = 0;
        for (int j = 0; j < 256; ++j) s += hist[tid * 256 + j];
        chunkSum[tid] = s;
    }
    __syncthreads();
    if (tid == 0) {
        unsigned int cum = 0; int cb;
        for (cb = 15; cb > 0; --cb) {
            if (cum + chunkSum[cb] >= 128u) break;
            cum += chunkSum[cb];
        }
        int bin;
        for (bin = cb * 256 + 255; bin > cb * 256; --bin) {
            if (cum + hist[bin] >= 128u) break;
            cum += hist[bin];
        }
        s_bin = bin; s_above = cum;
    }
    __syncthreads();

    const int tb = s_bin;
    for (int i = tid; i < D_SAE / 4; i += 256) {
        float4 v = *(const float4*)(rp + i * 4);
        float vv[4] = {v.x, v.y, v.z, v.w};
#pragma unroll
        for (int c = 0; c < 4; ++c) {
            const unsigned int k = fkey(vv[c]);
            const int bin = (int)(k >> 20);
            const int idx = i * 4 + c;
            if (bin > tb) {
                unsigned int p = atomicAdd(&s_cntHi, 1u);
                g_topidx[row * 128 + p] = idx;
                g_topval[row * 128 + p] = vv[c];
            } else if (bin == tb) {
                unsigned int q = atomicAdd(&s_cntCand, 1u);
                if (q < TK_CAP) cand[q] = makeComp(vv[c], idx);
            }
        }
    }
    __syncthreads();

    const int need = 128 - (int)s_cntHi;
    const int nc = min((int)s_cntCand, TK_CAP);
    for (int c = tid; c < nc; c += 256) {
        const unsigned long long me = cand[c];
        int r = 0;
        for (int j = 0; j < nc; ++j) r += (cand[j] > me);
        if (r < need) {
            const int pos = (int)s_cntHi + r;
            g_topidx[row * 128 + pos] = (int)(0xFFFFFFFFu - (unsigned int)me);
            g_topval[row * 128 + pos] = keyToFloat((unsigned int)(me >> 32));
        }
    }
}

// ======================================================================
// Kernel C: sequential scan. One CTA per batch row; exact top-64 from
// <=192 candidates (64 gated-prev + top128\prev) each step.
// ======================================================================
__global__ __launch_bounds__(256) void scan_kernel(const float* __restrict__ gate_raw) {
    __shared__ unsigned int bitmap[D_SAE / 32];  // 384 words
    __shared__ int prevIdx[KTOP];
    __shared__ float prevVal[KTOP];
    __shared__ unsigned long long cand[208];
    __shared__ int tmpIdx[KTOP];
    __shared__ float tmpVal[KTOP];
    __shared__ int s_ncand;

    const int b = blockIdx.x, tid = threadIdx.x;
    for (int i = tid; i < D_SAE / 32; i += 256) bitmap[i] = 0;
    int nprev = 0;
    __syncthreads();

    for (int t = 0; t < T_LEN; ++t) {
        const int row = b * T_LEN + t;
        if (tid == 0) s_ncand = nprev;
        __syncthreads();

        if (tid < nprev) {
            const int idx = prevIdx[tid];
            const float pre = g_pre[(size_t)row * D_SAE + idx];
            const float gate = 1.0f / (1.0f + expf(-gate_raw[idx]));
            const float y = gate * prevVal[tid] + pre;
            cand[tid] = makeComp(y, idx);
        }
        if (tid < 128) {
            const int idx = g_topidx[row * 128 + tid];
            if (!((bitmap[idx >> 5] >> (idx & 31)) & 1u)) {
                const int p = atomicAdd(&s_ncand, 1);
                cand[p] = makeComp(g_topval[row * 128 + tid], idx);
            }
        }
        __syncthreads();

        const int n = s_ncand;
        if (tid < n) {
            const unsigned long long me = cand[tid];
            int r = 0;
            for (int j = 0; j < n; ++j) r += (cand[j] > me);
            if (r < KTOP) {
                tmpIdx[r] = (int)(0xFFFFFFFFu - (unsigned int)me);
                tmpVal[r] = fmaxf(keyToFloat((unsigned int)(me >> 32)), 0.0f);
            }
        }
        __syncthreads();

        if (tid < nprev) atomicAnd(&bitmap[prevIdx[tid] >> 5], ~(1u << (prevIdx[tid] & 31)));
        __syncthreads();

        if (tid < KTOP) {
            const int idx = tmpIdx[tid];
            const float v = tmpVal[tid];
            prevIdx[tid] = idx; prevVal[tid] = v;
            atomicOr(&bitmap[idx >> 5], 1u << (idx & 31));
            g_zidx[row * KTOP + tid] = idx;
            g_zval[row * KTOP + tid] = v;
        }
        nprev = KTOP;
        __syncthreads();
    }
}

// ======================================================================
// Kernel D: sparse decode + per-row squared error.
// NOTE: xhat = d_out + 1 is only 4-byte aligned -> scalar stores only.
// ======================================================================
__global__ __launch_bounds__(192) void decode_kernel(const float* __restrict__ X,
                                                     const float* __restrict__ Wd,
                                                     const float* __restrict__ b_dec,
                                                     float* __restrict__ xhat) {
    __shared__ int sIdx[KTOP];
    __shared__ float sVal[KTOP];
    __shared__ float red[192];
    const int row = blockIdx.x, tid = threadIdx.x;
    if (tid < KTOP) {
        sIdx[tid] = g_zidx[row * KTOP + tid];
        sVal[tid] = g_zval[row * KTOP + tid];
    }
    __syncthreads();

    float4 acc = *(const float4*)(b_dec + tid * 4);
#pragma unroll 4
    for (int k = 0; k < KTOP; ++k) {
        const float v = sVal[k];
        const float4 w = *(const float4*)(Wd + (size_t)sIdx[k] * D_IN + tid * 4);
        acc.x += v * w.x; acc.y += v * w.y; acc.z += v * w.z; acc.w += v * w.w;
    }
    // scalar stores: xhat base is misaligned for float4 (d_out + 1 float)
    float* op = xhat + (size_t)row * D_IN + tid * 4;
    op[0] = acc.x; op[1] = acc.y; op[2] = acc.z; op[3] = acc.w;

    const float4 xv = *(const float4*)(X + (size_t)row * D_IN + tid * 4);
    const float dx = acc.x - xv.x, dy = acc.y - xv.y, dz = acc.z - xv.z, dw = acc.w - xv.w;
    red[tid] = dx * dx + dy * dy + dz * dz + dw * dw;
    __syncthreads();
    for (int s = 96; s >= 6; s >>= 1) {
        if (tid < s) red[tid] += red[tid + s];
        __syncthreads();
    }
    if (tid == 0) {
        float total = 0.f;
        for (int i = 0; i < 6; ++i) total += red[i];
        g_rowloss[row] = total;
    }
}

// ======================================================================
// Finalization
// ======================================================================
__global__ void zero_zlast(float* __restrict__ z) {
    const int i = blockIdx.x * blockDim.x + threadIdx.x;
    if (i < BATCH * D_SAE) z[i] = 0.0f;
}
__global__ void scatter_zlast(float* __restrict__ z) {
    const int gid = blockIdx.x * blockDim.x + threadIdx.x;
    if (gid < BATCH * KTOP) {
        const int b = gid >> 6, k = gid & 63;
        const int row = b * T_LEN + (T_LEN - 1);
        z[(size_t)b * D_SAE + g_zidx[row * KTOP + k]] = g_zval[row * KTOP + k];
    }
}
__global__ __launch_bounds__(1024) void loss_kernel(float* __restrict__ out) {
    __shared__ float red[1024];
    const int tid = threadIdx.x;
    red[tid] = g_rowloss[tid] + g_rowloss[tid + 1024];
    __syncthreads();
    for (int s = 512; s > 0; s >>= 1) {
        if (tid < s) red[tid] += red[tid + s];
        __syncthreads();
    }
    if (tid == 0) out[0] = red[0] / (float)NROWS;
}

// ======================================================================
extern "C" void kernel_launch(void* const* d_in, const int* in_sizes, int n_in,
                              void* d_out, int out_size) {
    const float* x        = (const float*)d_in[0];
    const float* W_enc    = (const float*)d_in[1];
    const float* W_dec    = (const float*)d_in[2];
    const float* b_enc    = (const float*)d_in[3];
    const float* b_dec    = (const float*)d_in[4];
    const float* gate_raw = (const float*)d_in[5];

    float* out       = (float*)d_out;
    float* out_loss  = out;
    float* out_xhat  = out + 1;
    float* out_zlast = out + 1 + (size_t)NROWS * D_IN;

    dim3 gGrid(D_SAE / 128, NROWS / 128);  // (96, 16)
    gemm_enc<<<gGrid, 256>>>(x, W_enc, b_enc);
    topk128<<<NROWS, 256>>>();
    scan_kernel<<<BATCH, 256>>>(gate_raw);
    decode_kernel<<<NROWS, 192>>>(x, W_dec, b_dec, out_xhat);
    zero_zlast<<<(BATCH * D_SAE + 255) / 256, 256>>>(out_zlast);
    scatter_zlast<<<(BATCH * KTOP + 255) / 256, 256>>>(out_zlast);
    loss_kernel<<<1, 1024>>>(out_loss);
}